// round 8
// baseline (speedup 1.0000x reference)
#include <cuda_runtime.h>
#include <cuda_fp16.h>
#include <cstdint>

#define NROWS 8192
#define DIN   256
#define DOUT  128
#define KC    64
#define TILE_M 128
#define NCTA  296
#define SLOTS 8

// ---- device-global scratch (no allocations allowed; zero-initialized) ----
__device__ __half g_h[(size_t)NROWS * DOUT];   // h fp16 row-major
__device__ float  g_B[NROWS];
__device__ float  g_D[NROWS];
__device__ float  g_E[NROWS];
__device__ float  g_acc[SLOTS][(size_t)NROWS * DOUT];  // slot partials (zero-init)
__device__ float  g_rs[SLOTS][NROWS];                  // rowsum partials (zero-init)

__device__ __forceinline__ uint32_t smem_u32(const void* p) {
    uint32_t a;
    asm("{ .reg .u64 t; cvta.to.shared.u64 t, %1; cvt.u32.u64 %0, t; }" : "=r"(a) : "l"(p));
    return a;
}

#define CP_ASYNC16(dst, src) \
    asm volatile("cp.async.cg.shared.global [%0], [%1], 16;" :: "r"(dst), "l"(src) : "memory")
#define CP_COMMIT() asm volatile("cp.async.commit_group;" ::: "memory")
#define CP_WAIT0()  asm volatile("cp.async.wait_group 0;" ::: "memory")

// ============ K1: h = xW + b -> g_h fp16, plus B/D/E vectors ============
#define K1_ROWS 16
#define XS_STR  20
#define WS_STR  132

__global__ __launch_bounds__(128) void k1_linear(
    const float* __restrict__ x, const float* __restrict__ W,
    const float* __restrict__ bW, const float* __restrict__ a1,
    const float* __restrict__ a2, const float* __restrict__ ba_p)
{
    __shared__ float xs[64 * XS_STR];
    __shared__ float ws[64 * WS_STR];

    const int tid  = threadIdx.x;
    const int wid  = tid >> 5;
    const int lane = tid & 31;
    const int rb = blockIdx.x * K1_ROWS;
    const int r0 = wid * 4;
    const int c0 = lane * 4;

    float acc[4][4];
    #pragma unroll
    for (int i = 0; i < 4; i++)
        #pragma unroll
        for (int j = 0; j < 4; j++) acc[i][j] = 0.f;

    for (int kc = 0; kc < DIN; kc += 64) {
        __syncthreads();
        #pragma unroll
        for (int e = tid; e < 256; e += 128) {
            int r = e >> 4, q = e & 15;
            float4 v = __ldg((const float4*)&x[(size_t)(rb + r) * DIN + kc + q * 4]);
            xs[(q * 4 + 0) * XS_STR + r] = v.x;
            xs[(q * 4 + 1) * XS_STR + r] = v.y;
            xs[(q * 4 + 2) * XS_STR + r] = v.z;
            xs[(q * 4 + 3) * XS_STR + r] = v.w;
        }
        #pragma unroll
        for (int e = tid; e < 2048; e += 128) {
            int k = e >> 5, cq = e & 31;
            *(float4*)&ws[k * WS_STR + cq * 4] =
                __ldg((const float4*)&W[(size_t)(kc + k) * DOUT + cq * 4]);
        }
        __syncthreads();

        #pragma unroll 8
        for (int k = 0; k < 64; k++) {
            float xr[4], wc[4];
            *(float4*)xr = *(const float4*)&xs[k * XS_STR + r0];
            *(float4*)wc = *(const float4*)&ws[k * WS_STR + c0];
            #pragma unroll
            for (int i = 0; i < 4; i++)
                #pragma unroll
                for (int j = 0; j < 4; j++)
                    acc[i][j] += xr[i] * wc[j];
        }
    }

    float bv[4];
    *(float4*)bv = __ldg((const float4*)&bW[c0]);
    #pragma unroll
    for (int i = 0; i < 4; i++)
        #pragma unroll
        for (int j = 0; j < 4; j++) acc[i][j] += bv[j];

    #pragma unroll
    for (int i = 0; i < 4; i++) {
        __half2 p0 = __floats2half2_rn(acc[i][0], acc[i][1]);
        __half2 p1 = __floats2half2_rn(acc[i][2], acc[i][3]);
        uint2 v = make_uint2(*(const uint32_t*)&p0, *(const uint32_t*)&p1);
        *(uint2*)(g_h + (size_t)(rb + r0 + i) * DOUT + c0) = v;
    }

    float a1v[4], a2v[4];
    *(float4*)a1v = __ldg((const float4*)&a1[c0]);
    *(float4*)a2v = __ldg((const float4*)&a2[c0]);
    float s1p[4], s2p[4];
    #pragma unroll
    for (int i = 0; i < 4; i++) {
        s1p[i] = acc[i][0]*a1v[0] + acc[i][1]*a1v[1] + acc[i][2]*a1v[2] + acc[i][3]*a1v[3];
        s2p[i] = acc[i][0]*a2v[0] + acc[i][1]*a2v[1] + acc[i][2]*a2v[2] + acc[i][3]*a2v[3];
    }
    #pragma unroll
    for (int m = 16; m >= 1; m >>= 1) {
        #pragma unroll
        for (int i = 0; i < 4; i++) {
            s1p[i] += __shfl_xor_sync(0xffffffffu, s1p[i], m);
            s2p[i] += __shfl_xor_sync(0xffffffffu, s2p[i], m);
        }
    }
    if (lane == 0) {
        const float bav = ba_p[0];
        #pragma unroll
        for (int i = 0; i < 4; i++) {
            int row = rb + r0 + i;
            float u = s1p[i] + bav;
            g_E[row] = expf(-0.99f * u);
            g_B[row] = expf(s2p[i]);
            g_D[row] = expf(0.01f * s2p[i]);
        }
    }
}

// ============ K2: fused masked-softmax-numerator GEMM ============
// 296 CTAs, balanced flattened (tile, chunk) ranges, double-buffered smem,
// adj reg-prefetch + cp.async h across MMA, fp16-accum HMMA (flush every 2 chunks).
#define PSTR 72u
#define HSTR 136u
#define PBUF (128u * PSTR * 2u)   // 18432 B
#define HBUF (64u * HSTR * 2u)    // 17408 B
#define SMEM_K2 (2 * 18432 + 2 * 17408)  // 71680 B

__global__ __launch_bounds__(256, 2) void k2_fused(const int* __restrict__ adj)
{
    extern __shared__ char smem[];
    const uint32_t sPb = smem_u32(smem);
    const uint32_t sHb = sPb + 2u * PBUF;

    const int tid  = threadIdx.x;
    const int wid  = tid >> 5;
    const int lane = tid & 31;
    const int cta  = blockIdx.x;
    const int slot = cta & 7;

    // balanced flattened chunk range: [s, e) out of 64*128 = 8192 chunk-units
    const int s = (1024 * cta) / 37;          // = cta*8192/296
    const int e = (1024 * (cta + 1)) / 37;

    // P'/adj mapping: thread owns rows tr+32k (k=0..3), j's jq8*8..+8
    const int tr  = tid >> 3;      // 0..31
    const int jq8 = tid & 7;       // 0..7

    // h cp.async mapping: thread copies 64B of j-row hjr
    const int hjr = tid >> 2;            // 0..63
    const int hcb = (tid & 3) * 64;      // byte offset in 256B row

    // ldmatrix lane addressing
    const int g  = lane >> 3;
    const int l7 = lane & 7;
    const uint32_t aRowOff  = (uint32_t)(wid * 16 + (g & 1) * 8 + l7) * PSTR + (uint32_t)((g >> 1) * 8);
    const uint32_t bRowBase = (uint32_t)((g & 1) * 8 + l7) * HSTR + (uint32_t)((g >> 1) * 8);

    const uint32_t sPst = ((uint32_t)tr * PSTR + (uint32_t)jq8 * 8u) * 2u;
    const uint32_t sHst = (uint32_t)hjr * HSTR * 2u + (uint32_t)hcb;

    const float* Bp = g_B + jq8 * 8;
    const float* Dp = g_D + jq8 * 8;

    const int t0 = s >> 7, t1 = (e - 1) >> 7;
    for (int t = t0; t <= t1; ++t) {
        const int c0 = (s > (t << 7)) ? s : (t << 7);
        const int c1 = (e < ((t + 1) << 7)) ? e : ((t + 1) << 7);
        const int rowb = t * TILE_M;

        float Ei[4];
        #pragma unroll
        for (int k = 0; k < 4; k++) Ei[k] = g_E[rowb + tr + 32 * k];

        const int* adjbase = adj + (size_t)(rowb + tr) * NROWS + jq8 * 8;

        float facc[16][4];
        uint32_t hacc[16][2];
        #pragma unroll
        for (int n = 0; n < 16; n++) {
            #pragma unroll
            for (int c = 0; c < 4; c++) facc[n][c] = 0.f;
            hacc[n][0] = 0u; hacc[n][1] = 0u;
        }
        float rsum[4] = {0.f, 0.f, 0.f, 0.f};

        int4 adjr[8];

        // P' producer (uses adjr, Ei; writes sP at stb)
        auto produce = [&](int jb, uint32_t stb) {
            float4 B0 = __ldg((const float4*)(Bp + jb));
            float4 B1 = __ldg((const float4*)(Bp + jb + 4));
            float4 D0 = __ldg((const float4*)(Dp + jb));
            float4 D1 = __ldg((const float4*)(Dp + jb + 4));
            #pragma unroll
            for (int k = 0; k < 4; k++) {
                int4 a0 = adjr[2 * k], a1 = adjr[2 * k + 1];
                float v0 = fmaxf(B0.x, Ei[k] * D0.x); v0 = a0.x ? v0 : 0.f;
                float v1 = fmaxf(B0.y, Ei[k] * D0.y); v1 = a0.y ? v1 : 0.f;
                float v2 = fmaxf(B0.z, Ei[k] * D0.z); v2 = a0.z ? v2 : 0.f;
                float v3 = fmaxf(B0.w, Ei[k] * D0.w); v3 = a0.w ? v3 : 0.f;
                float v4 = fmaxf(B1.x, Ei[k] * D1.x); v4 = a1.x ? v4 : 0.f;
                float v5 = fmaxf(B1.y, Ei[k] * D1.y); v5 = a1.y ? v5 : 0.f;
                float v6 = fmaxf(B1.z, Ei[k] * D1.z); v6 = a1.z ? v6 : 0.f;
                float v7 = fmaxf(B1.w, Ei[k] * D1.w); v7 = a1.w ? v7 : 0.f;
                rsum[k] += ((v0 + v1) + (v2 + v3)) + ((v4 + v5) + (v6 + v7));
                __half2 p0 = __floats2half2_rn(v0, v1);
                __half2 p1 = __floats2half2_rn(v2, v3);
                __half2 p2 = __floats2half2_rn(v4, v5);
                __half2 p3 = __floats2half2_rn(v6, v7);
                asm volatile("st.shared.v4.b32 [%0], {%1,%2,%3,%4};"
                    :: "r"(stb + (uint32_t)(32 * k) * PSTR * 2u),
                       "r"(*(const uint32_t*)&p0), "r"(*(const uint32_t*)&p1),
                       "r"(*(const uint32_t*)&p2), "r"(*(const uint32_t*)&p3) : "memory");
            }
        };

        // ---- prologue: stage chunk c0 into buffer 0 ----
        {
            const int jb = (c0 & 127) * KC;
            #pragma unroll
            for (int k = 0; k < 4; k++) {
                const int4* p = (const int4*)(adjbase + (size_t)(32 * k) * NROWS + jb);
                adjr[2 * k]     = __ldg(p);
                adjr[2 * k + 1] = __ldg(p + 1);
            }
            const char* hsrc = (const char*)g_h + ((size_t)(jb + hjr) * DOUT) * 2 + hcb;
            #pragma unroll
            for (int q = 0; q < 4; q++)
                CP_ASYNC16(sHb + sHst + (uint32_t)q * 16u, hsrc + q * 16);
            CP_COMMIT(); CP_WAIT0();
            produce(jb, sPb + sPst);
        }
        __syncthreads();

        for (int cc = c0; cc < c1; ++cc) {
            const int b = (cc - c0) & 1;
            const uint32_t Pcur = sPb + (uint32_t)b * PBUF;
            const uint32_t Hcur = sHb + (uint32_t)b * HBUF;
            const uint32_t Pnxt = sPb + (uint32_t)(b ^ 1) * PBUF;
            const uint32_t Hnxt = sHb + (uint32_t)(b ^ 1) * HBUF;
            const bool more = (cc + 1 < c1);
            const int jbn = ((cc + 1) & 127) * KC;

            if (more) {
                #pragma unroll
                for (int k = 0; k < 4; k++) {
                    const int4* p = (const int4*)(adjbase + (size_t)(32 * k) * NROWS + jbn);
                    adjr[2 * k]     = __ldg(p);
                    adjr[2 * k + 1] = __ldg(p + 1);
                }
                const char* hsrc = (const char*)g_h + ((size_t)(jbn + hjr) * DOUT) * 2 + hcb;
                #pragma unroll
                for (int q = 0; q < 4; q++)
                    CP_ASYNC16(Hnxt + sHst + (uint32_t)q * 16u, hsrc + q * 16);
                CP_COMMIT();
            }

            // ---- HMMA fp16-accum on current buffers ----
            #pragma unroll
            for (int ss = 0; ss < 4; ++ss) {
                uint32_t a0, a1, a2, a3;
                asm volatile("ldmatrix.sync.aligned.m8n8.x4.shared.b16 {%0,%1,%2,%3}, [%4];"
                    : "=r"(a0), "=r"(a1), "=r"(a2), "=r"(a3)
                    : "r"(Pcur + (aRowOff + (uint32_t)ss * 16u) * 2u));
                #pragma unroll
                for (int np = 0; np < 8; ++np) {
                    uint32_t b0, b1, b2, b3;
                    asm volatile("ldmatrix.sync.aligned.m8n8.x4.trans.shared.b16 {%0,%1,%2,%3}, [%4];"
                        : "=r"(b0), "=r"(b1), "=r"(b2), "=r"(b3)
                        : "r"(Hcur + (bRowBase + (uint32_t)ss * 16u * HSTR + (uint32_t)np * 16u) * 2u));
                    asm volatile("mma.sync.aligned.m16n8k16.row.col.f16.f16.f16.f16 "
                        "{%0,%1}, {%2,%3,%4,%5}, {%6,%7}, {%0,%1};"
                        : "+r"(hacc[np * 2][0]), "+r"(hacc[np * 2][1])
                        : "r"(a0), "r"(a1), "r"(a2), "r"(a3), "r"(b0), "r"(b1));
                    asm volatile("mma.sync.aligned.m16n8k16.row.col.f16.f16.f16.f16 "
                        "{%0,%1}, {%2,%3,%4,%5}, {%6,%7}, {%0,%1};"
                        : "+r"(hacc[np * 2 + 1][0]), "+r"(hacc[np * 2 + 1][1])
                        : "r"(a0), "r"(a1), "r"(a2), "r"(a3), "r"(b2), "r"(b3));
                }
            }

            // ---- flush fp16 accumulators to fp32 every 2 chunks / at segment end ----
            if (((cc - c0) & 1) || (cc == c1 - 1)) {
                #pragma unroll
                for (int n = 0; n < 16; n++) {
                    float2 lo = __half22float2(*(const __half2*)&hacc[n][0]);
                    float2 hi = __half22float2(*(const __half2*)&hacc[n][1]);
                    facc[n][0] += lo.x; facc[n][1] += lo.y;
                    facc[n][2] += hi.x; facc[n][3] += hi.y;
                    hacc[n][0] = 0u; hacc[n][1] = 0u;
                }
            }

            if (more) produce(jbn, Pnxt + sPst);
            CP_WAIT0();
            __syncthreads();
        }

        // ---- flush partials for this tile into slot buffers ----
        {
            const int r  = lane >> 2;
            const int c2 = (lane & 3) * 2;
            const int row0 = rowb + wid * 16 + r;
            float* dst0 = &g_acc[slot][(size_t)row0 * DOUT];
            float* dst1 = dst0 + (size_t)8 * DOUT;
            #pragma unroll
            for (int nt = 0; nt < 16; ++nt) {
                int col = nt * 8 + c2;
                *(float2*)(dst0 + col) = make_float2(facc[nt][0], facc[nt][1]);
                *(float2*)(dst1 + col) = make_float2(facc[nt][2], facc[nt][3]);
            }
        }
        #pragma unroll
        for (int m = 1; m <= 4; m <<= 1) {
            #pragma unroll
            for (int k = 0; k < 4; k++)
                rsum[k] += __shfl_xor_sync(0xffffffffu, rsum[k], m);
        }
        if (jq8 == 0) {
            #pragma unroll
            for (int k = 0; k < 4; k++)
                g_rs[slot][rowb + tr + 32 * k] = rsum[k];
        }
        __syncthreads();   // smem reuse safety across segments
    }
}

// ============ K3: sum slot partials, normalize ============
__global__ __launch_bounds__(256) void k3_final(float* __restrict__ out)
{
    const int idx = blockIdx.x * 256 + threadIdx.x;   // float4 index
    const int row = idx >> 5;                         // 32 float4 per row
    float rs = 0.f;
    #pragma unroll
    for (int s2 = 0; s2 < SLOTS; s2++) rs += g_rs[s2][row];
    const float inv = 1.0f / rs;
    float ox = 0.f, oy = 0.f, oz = 0.f, ow = 0.f;
    #pragma unroll
    for (int s2 = 0; s2 < SLOTS; s2++) {
        float4 a = ((const float4*)g_acc[s2])[idx];
        ox += a.x; oy += a.y; oz += a.z; ow += a.w;
    }
    float4 o;
    o.x = ox * inv; o.y = oy * inv; o.z = oz * inv; o.w = ow * inv;
    ((float4*)out)[idx] = o;
}

extern "C" void kernel_launch(void* const* d_in, const int* in_sizes, int n_in,
                              void* d_out, int out_size) {
    const float* x   = (const float*)d_in[0];
    const int*   adj = (const int*)  d_in[1];
    const float* W   = (const float*)d_in[2];
    const float* bW  = (const float*)d_in[3];
    const float* a1  = (const float*)d_in[4];
    const float* a2  = (const float*)d_in[5];
    const float* ba  = (const float*)d_in[6];
    float* out = (float*)d_out;

    static bool attr_set = false;
    if (!attr_set) {
        cudaFuncSetAttribute(k2_fused, cudaFuncAttributeMaxDynamicSharedMemorySize, SMEM_K2);
        attr_set = true;
    }

    k1_linear<<<NROWS / K1_ROWS, 128>>>(x, W, bW, a1, a2, ba);
    k2_fused<<<NCTA, 256, SMEM_K2>>>(adj);
    k3_final<<<(NROWS * DOUT / 4) / 256, 256>>>(out);
}

// round 9
// speedup vs baseline: 1.2134x; 1.2134x over previous
#include <cuda_runtime.h>
#include <cuda_fp16.h>
#include <cstdint>

#define NROWS 8192
#define DIN   256
#define DOUT  128
#define KC    64
#define TILE_M 128
#define NCTA  296
#define SLOTS 8

// ---- device-global scratch (no allocations allowed; zero-initialized) ----
__device__ __half g_h[(size_t)NROWS * DOUT];   // h fp16 row-major
__device__ float  g_B[NROWS];
__device__ float  g_D[NROWS];
__device__ float  g_E[NROWS];
__device__ float  g_acc[SLOTS][(size_t)NROWS * DOUT];  // slot partials (zero-init)
__device__ float  g_rs[SLOTS][NROWS];                  // rowsum partials (zero-init)

__device__ __forceinline__ uint32_t smem_u32(const void* p) {
    uint32_t a;
    asm("{ .reg .u64 t; cvta.to.shared.u64 t, %1; cvt.u32.u64 %0, t; }" : "=r"(a) : "l"(p));
    return a;
}

#define CP_ASYNC16(dst, src) \
    asm volatile("cp.async.cg.shared.global [%0], [%1], 16;" :: "r"(dst), "l"(src) : "memory")
#define CP_COMMIT() asm volatile("cp.async.commit_group;" ::: "memory")
#define CP_WAIT0()  asm volatile("cp.async.wait_group 0;" ::: "memory")

// ============ K1: h = xW + b -> g_h fp16, plus B/D/E vectors ============
#define K1_ROWS 16
#define XS_STR  20
#define WS_STR  132

__global__ __launch_bounds__(128) void k1_linear(
    const float* __restrict__ x, const float* __restrict__ W,
    const float* __restrict__ bW, const float* __restrict__ a1,
    const float* __restrict__ a2, const float* __restrict__ ba_p)
{
    __shared__ float xs[64 * XS_STR];
    __shared__ float ws[64 * WS_STR];

    const int tid  = threadIdx.x;
    const int wid  = tid >> 5;
    const int lane = tid & 31;
    const int rb = blockIdx.x * K1_ROWS;
    const int r0 = wid * 4;
    const int c0 = lane * 4;

    float acc[4][4];
    #pragma unroll
    for (int i = 0; i < 4; i++)
        #pragma unroll
        for (int j = 0; j < 4; j++) acc[i][j] = 0.f;

    for (int kc = 0; kc < DIN; kc += 64) {
        __syncthreads();
        #pragma unroll
        for (int e = tid; e < 256; e += 128) {
            int r = e >> 4, q = e & 15;
            float4 v = __ldg((const float4*)&x[(size_t)(rb + r) * DIN + kc + q * 4]);
            xs[(q * 4 + 0) * XS_STR + r] = v.x;
            xs[(q * 4 + 1) * XS_STR + r] = v.y;
            xs[(q * 4 + 2) * XS_STR + r] = v.z;
            xs[(q * 4 + 3) * XS_STR + r] = v.w;
        }
        #pragma unroll
        for (int e = tid; e < 2048; e += 128) {
            int k = e >> 5, cq = e & 31;
            *(float4*)&ws[k * WS_STR + cq * 4] =
                __ldg((const float4*)&W[(size_t)(kc + k) * DOUT + cq * 4]);
        }
        __syncthreads();

        #pragma unroll 8
        for (int k = 0; k < 64; k++) {
            float xr[4], wc[4];
            *(float4*)xr = *(const float4*)&xs[k * XS_STR + r0];
            *(float4*)wc = *(const float4*)&ws[k * WS_STR + c0];
            #pragma unroll
            for (int i = 0; i < 4; i++)
                #pragma unroll
                for (int j = 0; j < 4; j++)
                    acc[i][j] += xr[i] * wc[j];
        }
    }

    float bv[4];
    *(float4*)bv = __ldg((const float4*)&bW[c0]);
    #pragma unroll
    for (int i = 0; i < 4; i++)
        #pragma unroll
        for (int j = 0; j < 4; j++) acc[i][j] += bv[j];

    #pragma unroll
    for (int i = 0; i < 4; i++) {
        __half2 p0 = __floats2half2_rn(acc[i][0], acc[i][1]);
        __half2 p1 = __floats2half2_rn(acc[i][2], acc[i][3]);
        uint2 v = make_uint2(*(const uint32_t*)&p0, *(const uint32_t*)&p1);
        *(uint2*)(g_h + (size_t)(rb + r0 + i) * DOUT + c0) = v;
    }

    float a1v[4], a2v[4];
    *(float4*)a1v = __ldg((const float4*)&a1[c0]);
    *(float4*)a2v = __ldg((const float4*)&a2[c0]);
    float s1p[4], s2p[4];
    #pragma unroll
    for (int i = 0; i < 4; i++) {
        s1p[i] = acc[i][0]*a1v[0] + acc[i][1]*a1v[1] + acc[i][2]*a1v[2] + acc[i][3]*a1v[3];
        s2p[i] = acc[i][0]*a2v[0] + acc[i][1]*a2v[1] + acc[i][2]*a2v[2] + acc[i][3]*a2v[3];
    }
    #pragma unroll
    for (int m = 16; m >= 1; m >>= 1) {
        #pragma unroll
        for (int i = 0; i < 4; i++) {
            s1p[i] += __shfl_xor_sync(0xffffffffu, s1p[i], m);
            s2p[i] += __shfl_xor_sync(0xffffffffu, s2p[i], m);
        }
    }
    if (lane == 0) {
        const float bav = ba_p[0];
        #pragma unroll
        for (int i = 0; i < 4; i++) {
            int row = rb + r0 + i;
            float u = s1p[i] + bav;
            g_E[row] = expf(-0.99f * u);
            g_B[row] = expf(s2p[i]);
            g_D[row] = expf(0.01f * s2p[i]);
        }
    }
}

// ============ K2: fused masked-softmax-numerator GEMM ============
// 296 CTAs, balanced flattened ranges, double-buffered smem,
// adj reg-prefetch + cp.async h across MMA, fp32-accum HMMA.
// Warp tile = 32 rows x 64 cols (4 m-stripes x 2 n-halves): 24 LDSM / 64 MMA.
#define PSTR 72u
#define HSTR 136u
#define PBUF (128u * PSTR * 2u)   // 18432 B
#define HBUF (64u * HSTR * 2u)    // 17408 B
#define SMEM_K2 (2 * 18432 + 2 * 17408)  // 71680 B

__global__ __launch_bounds__(256, 2) void k2_fused(const int* __restrict__ adj)
{
    extern __shared__ char smem[];
    const uint32_t sPb = smem_u32(smem);
    const uint32_t sHb = sPb + 2u * PBUF;

    const int tid  = threadIdx.x;
    const int wid  = tid >> 5;
    const int lane = tid & 31;
    const int cta  = blockIdx.x;
    const int slot = cta & 7;

    // balanced flattened chunk range: [s, e) out of 64*128 = 8192 chunk-units
    const int s = (1024 * cta) / 37;          // = cta*8192/296
    const int e = (1024 * (cta + 1)) / 37;

    // P'/adj mapping: thread owns rows tr+32k (k=0..3), j's jq8*8..+8
    const int tr  = tid >> 3;      // 0..31
    const int jq8 = tid & 7;       // 0..7

    // h cp.async mapping: thread copies 64B of j-row hjr
    const int hjr = tid >> 2;            // 0..63
    const int hcb = (tid & 3) * 64;      // byte offset in 256B row

    // warp tile: mwarp in 0..3 (32-row stripe), nwarp in 0..1 (64-col half)
    const int mwarp = wid & 3;
    const int nwarp = wid >> 2;
    const uint32_t ncol0 = (uint32_t)nwarp * 64u;

    // ldmatrix lane addressing (half units)
    const int g  = lane >> 3;
    const int l7 = lane & 7;
    const uint32_t aRow0 = (uint32_t)(mwarp * 32 + (g & 1) * 8 + l7) * PSTR + (uint32_t)((g >> 1) * 8);
    const uint32_t aRow1 = aRow0 + 16u * PSTR;
    const uint32_t bBase = (uint32_t)((g & 1) * 8 + l7) * HSTR + (uint32_t)((g >> 1) * 8) + ncol0;

    const uint32_t sPst = ((uint32_t)tr * PSTR + (uint32_t)jq8 * 8u) * 2u;
    const uint32_t sHst = (uint32_t)hjr * HSTR * 2u + (uint32_t)hcb;

    const float* Bp = g_B + jq8 * 8;
    const float* Dp = g_D + jq8 * 8;

    const int t0 = s >> 7, t1 = (e - 1) >> 7;
    for (int t = t0; t <= t1; ++t) {
        const int c0 = (s > (t << 7)) ? s : (t << 7);
        const int c1 = (e < ((t + 1) << 7)) ? e : ((t + 1) << 7);
        const int rowb = t * TILE_M;

        float Ei[4];
        #pragma unroll
        for (int k = 0; k < 4; k++) Ei[k] = g_E[rowb + tr + 32 * k];

        const int* adjbase = adj + (size_t)(rowb + tr) * NROWS + jq8 * 8;

        // facc[mt*8 + nt*2 + hh][4]
        float facc[16][4];
        #pragma unroll
        for (int n = 0; n < 16; n++)
            #pragma unroll
            for (int c = 0; c < 4; c++) facc[n][c] = 0.f;
        float rsum[4] = {0.f, 0.f, 0.f, 0.f};

        int4 adjr[8];

        // P' producer (uses adjr, Ei; writes sP at stb)
        auto produce = [&](int jb, uint32_t stb) {
            float4 B0 = __ldg((const float4*)(Bp + jb));
            float4 B1 = __ldg((const float4*)(Bp + jb + 4));
            float4 D0 = __ldg((const float4*)(Dp + jb));
            float4 D1 = __ldg((const float4*)(Dp + jb + 4));
            #pragma unroll
            for (int k = 0; k < 4; k++) {
                int4 a0 = adjr[2 * k], a1 = adjr[2 * k + 1];
                float v0 = fmaxf(B0.x, Ei[k] * D0.x); v0 = a0.x ? v0 : 0.f;
                float v1 = fmaxf(B0.y, Ei[k] * D0.y); v1 = a0.y ? v1 : 0.f;
                float v2 = fmaxf(B0.z, Ei[k] * D0.z); v2 = a0.z ? v2 : 0.f;
                float v3 = fmaxf(B0.w, Ei[k] * D0.w); v3 = a0.w ? v3 : 0.f;
                float v4 = fmaxf(B1.x, Ei[k] * D1.x); v4 = a1.x ? v4 : 0.f;
                float v5 = fmaxf(B1.y, Ei[k] * D1.y); v5 = a1.y ? v5 : 0.f;
                float v6 = fmaxf(B1.z, Ei[k] * D1.z); v6 = a1.z ? v6 : 0.f;
                float v7 = fmaxf(B1.w, Ei[k] * D1.w); v7 = a1.w ? v7 : 0.f;
                rsum[k] += ((v0 + v1) + (v2 + v3)) + ((v4 + v5) + (v6 + v7));
                __half2 p0 = __floats2half2_rn(v0, v1);
                __half2 p1 = __floats2half2_rn(v2, v3);
                __half2 p2 = __floats2half2_rn(v4, v5);
                __half2 p3 = __floats2half2_rn(v6, v7);
                asm volatile("st.shared.v4.b32 [%0], {%1,%2,%3,%4};"
                    :: "r"(stb + (uint32_t)(32 * k) * PSTR * 2u),
                       "r"(*(const uint32_t*)&p0), "r"(*(const uint32_t*)&p1),
                       "r"(*(const uint32_t*)&p2), "r"(*(const uint32_t*)&p3) : "memory");
            }
        };

        // ---- prologue: stage chunk c0 into buffer 0 ----
        {
            const int jb = (c0 & 127) * KC;
            #pragma unroll
            for (int k = 0; k < 4; k++) {
                const int4* p = (const int4*)(adjbase + (size_t)(32 * k) * NROWS + jb);
                adjr[2 * k]     = __ldg(p);
                adjr[2 * k + 1] = __ldg(p + 1);
            }
            const char* hsrc = (const char*)g_h + ((size_t)(jb + hjr) * DOUT) * 2 + hcb;
            #pragma unroll
            for (int q = 0; q < 4; q++)
                CP_ASYNC16(sHb + sHst + (uint32_t)q * 16u, hsrc + q * 16);
            CP_COMMIT(); CP_WAIT0();
            produce(jb, sPb + sPst);
        }
        __syncthreads();

        for (int cc = c0; cc < c1; ++cc) {
            const int b = (cc - c0) & 1;
            const uint32_t Pcur = sPb + (uint32_t)b * PBUF;
            const uint32_t Hcur = sHb + (uint32_t)b * HBUF;
            const uint32_t Pnxt = sPb + (uint32_t)(b ^ 1) * PBUF;
            const uint32_t Hnxt = sHb + (uint32_t)(b ^ 1) * HBUF;
            const bool more = (cc + 1 < c1);
            const int jbn = ((cc + 1) & 127) * KC;

            if (more) {
                #pragma unroll
                for (int k = 0; k < 4; k++) {
                    const int4* p = (const int4*)(adjbase + (size_t)(32 * k) * NROWS + jbn);
                    adjr[2 * k]     = __ldg(p);
                    adjr[2 * k + 1] = __ldg(p + 1);
                }
                const char* hsrc = (const char*)g_h + ((size_t)(jbn + hjr) * DOUT) * 2 + hcb;
                #pragma unroll
                for (int q = 0; q < 4; q++)
                    CP_ASYNC16(Hnxt + sHst + (uint32_t)q * 16u, hsrc + q * 16);
                CP_COMMIT();
            }

            // ---- HMMA fp32-accum, warp tile 32x64 ----
            #pragma unroll
            for (int ss = 0; ss < 4; ++ss) {
                uint32_t A0[4], A1[4];
                asm volatile("ldmatrix.sync.aligned.m8n8.x4.shared.b16 {%0,%1,%2,%3}, [%4];"
                    : "=r"(A0[0]), "=r"(A0[1]), "=r"(A0[2]), "=r"(A0[3])
                    : "r"(Pcur + (aRow0 + (uint32_t)ss * 16u) * 2u));
                asm volatile("ldmatrix.sync.aligned.m8n8.x4.shared.b16 {%0,%1,%2,%3}, [%4];"
                    : "=r"(A1[0]), "=r"(A1[1]), "=r"(A1[2]), "=r"(A1[3])
                    : "r"(Pcur + (aRow1 + (uint32_t)ss * 16u) * 2u));
                #pragma unroll
                for (int nt = 0; nt < 4; ++nt) {
                    uint32_t b0, b1, b2, b3;
                    asm volatile("ldmatrix.sync.aligned.m8n8.x4.trans.shared.b16 {%0,%1,%2,%3}, [%4];"
                        : "=r"(b0), "=r"(b1), "=r"(b2), "=r"(b3)
                        : "r"(Hcur + (bBase + (uint32_t)ss * 16u * HSTR + (uint32_t)nt * 16u) * 2u));
                    float* d00 = facc[nt * 2];
                    float* d01 = facc[nt * 2 + 1];
                    float* d10 = facc[8 + nt * 2];
                    float* d11 = facc[8 + nt * 2 + 1];
                    asm volatile("mma.sync.aligned.m16n8k16.row.col.f32.f16.f16.f32 "
                        "{%0,%1,%2,%3}, {%4,%5,%6,%7}, {%8,%9}, {%0,%1,%2,%3};"
                        : "+f"(d00[0]), "+f"(d00[1]), "+f"(d00[2]), "+f"(d00[3])
                        : "r"(A0[0]), "r"(A0[1]), "r"(A0[2]), "r"(A0[3]), "r"(b0), "r"(b1));
                    asm volatile("mma.sync.aligned.m16n8k16.row.col.f32.f16.f16.f32 "
                        "{%0,%1,%2,%3}, {%4,%5,%6,%7}, {%8,%9}, {%0,%1,%2,%3};"
                        : "+f"(d01[0]), "+f"(d01[1]), "+f"(d01[2]), "+f"(d01[3])
                        : "r"(A0[0]), "r"(A0[1]), "r"(A0[2]), "r"(A0[3]), "r"(b2), "r"(b3));
                    asm volatile("mma.sync.aligned.m16n8k16.row.col.f32.f16.f16.f32 "
                        "{%0,%1,%2,%3}, {%4,%5,%6,%7}, {%8,%9}, {%0,%1,%2,%3};"
                        : "+f"(d10[0]), "+f"(d10[1]), "+f"(d10[2]), "+f"(d10[3])
                        : "r"(A1[0]), "r"(A1[1]), "r"(A1[2]), "r"(A1[3]), "r"(b0), "r"(b1));
                    asm volatile("mma.sync.aligned.m16n8k16.row.col.f32.f16.f16.f32 "
                        "{%0,%1,%2,%3}, {%4,%5,%6,%7}, {%8,%9}, {%0,%1,%2,%3};"
                        : "+f"(d11[0]), "+f"(d11[1]), "+f"(d11[2]), "+f"(d11[3])
                        : "r"(A1[0]), "r"(A1[1]), "r"(A1[2]), "r"(A1[3]), "r"(b2), "r"(b3));
                }
            }

            if (more) produce(jbn, Pnxt + sPst);
            CP_WAIT0();
            __syncthreads();
        }

        // ---- flush partials for this tile into slot buffers ----
        {
            const int r  = lane >> 2;
            const int c2 = (lane & 3) * 2;
            #pragma unroll
            for (int mt = 0; mt < 2; ++mt) {
                const int row0 = rowb + mwarp * 32 + mt * 16 + r;
                float* dst0 = &g_acc[slot][(size_t)row0 * DOUT];
                float* dst1 = dst0 + (size_t)8 * DOUT;
                #pragma unroll
                for (int nt = 0; nt < 4; ++nt) {
                    #pragma unroll
                    for (int hh = 0; hh < 2; ++hh) {
                        const float* f = facc[mt * 8 + nt * 2 + hh];
                        int col = nwarp * 64 + nt * 16 + hh * 8 + c2;
                        *(float2*)(dst0 + col) = make_float2(f[0], f[1]);
                        *(float2*)(dst1 + col) = make_float2(f[2], f[3]);
                    }
                }
            }
        }
        #pragma unroll
        for (int m = 1; m <= 4; m <<= 1) {
            #pragma unroll
            for (int k = 0; k < 4; k++)
                rsum[k] += __shfl_xor_sync(0xffffffffu, rsum[k], m);
        }
        if (jq8 == 0) {
            #pragma unroll
            for (int k = 0; k < 4; k++)
                g_rs[slot][rowb + tr + 32 * k] = rsum[k];
        }
        __syncthreads();   // smem reuse safety across segments
    }
}

// ============ K3: sum slot partials, normalize ============
__global__ __launch_bounds__(256) void k3_final(float* __restrict__ out)
{
    const int idx = blockIdx.x * 256 + threadIdx.x;   // float4 index
    const int row = idx >> 5;                         // 32 float4 per row
    float rs = 0.f;
    #pragma unroll
    for (int s2 = 0; s2 < SLOTS; s2++) rs += g_rs[s2][row];
    const float inv = 1.0f / rs;
    float ox = 0.f, oy = 0.f, oz = 0.f, ow = 0.f;
    #pragma unroll
    for (int s2 = 0; s2 < SLOTS; s2++) {
        float4 a = ((const float4*)g_acc[s2])[idx];
        ox += a.x; oy += a.y; oz += a.z; ow += a.w;
    }
    float4 o;
    o.x = ox * inv; o.y = oy * inv; o.z = oz * inv; o.w = ow * inv;
    ((float4*)out)[idx] = o;
}

extern "C" void kernel_launch(void* const* d_in, const int* in_sizes, int n_in,
                              void* d_out, int out_size) {
    const float* x   = (const float*)d_in[0];
    const int*   adj = (const int*)  d_in[1];
    const float* W   = (const float*)d_in[2];
    const float* bW  = (const float*)d_in[3];
    const float* a1  = (const float*)d_in[4];
    const float* a2  = (const float*)d_in[5];
    const float* ba  = (const float*)d_in[6];
    float* out = (float*)d_out;

    static bool attr_set = false;
    if (!attr_set) {
        cudaFuncSetAttribute(k2_fused, cudaFuncAttributeMaxDynamicSharedMemorySize, SMEM_K2);
        attr_set = true;
    }

    k1_linear<<<NROWS / K1_ROWS, 128>>>(x, W, bW, a1, a2, ba);
    k2_fused<<<NCTA, 256, SMEM_K2>>>(adj);
    k3_final<<<(NROWS * DOUT / 4) / 256, 256>>>(out);
}